// round 7
// baseline (speedup 1.0000x reference)
#include <cuda_runtime.h>

#define HID 24
#define TPB 64

typedef unsigned long long u64;

// Packed W_hh in GLOBAL memory, line-coalesced:
// entry (j, i, b) at ulonglong2 index (j*6+i)*8 + b  -> per (j,i) the 8 groups
// form one 128-byte line, so one warp LDG.128 = 1-2 wavefronts.
__device__ __align__(128) static u64 g_wq[864];   // 432 ulonglong2 = 6912 B

__device__ __forceinline__ u64 pack2(float x, float y) {
    u64 r; asm("mov.b64 %0, {%1, %2};" : "=l"(r) : "f"(x), "f"(y)); return r;
}
__device__ __forceinline__ void unpack2(u64 v, float &x, float &y) {
    asm("mov.b64 {%0, %1}, %2;" : "=f"(x), "=f"(y) : "l"(v));
}
__device__ __forceinline__ u64 ffma2(u64 a, u64 b, u64 c) {
    u64 d; asm("fma.rn.f32x2 %0, %1, %2, %3;" : "=l"(d) : "l"(a), "l"(b), "l"(c)); return d;
}
__device__ __forceinline__ u64 fmul2(u64 a, u64 b) {
    u64 d; asm("mul.rn.f32x2 %0, %1, %2;" : "=l"(d) : "l"(a), "l"(b)); return d;
}
__device__ __forceinline__ u64 fadd2(u64 a, u64 b) {
    u64 d; asm("add.rn.f32x2 %0, %1, %2;" : "=l"(d) : "l"(a), "l"(b)); return d;
}
__device__ __forceinline__ float ex2a(float x) {
    float r; asm("ex2.approx.f32 %0, %1;" : "=f"(r) : "f"(x)); return r;
}
__device__ __forceinline__ float rcpa(float x) {
    float r; asm("rcp.approx.f32 %0, %1;" : "=f"(r) : "f"(x)); return r;
}

// Prep: pack W_hh into g_wq. b = q*2+kg selects (row-quarter, k-half);
// j = gate*3+p -> rows r0 = gate*24 + 6q + 2p; i selects k pair u0 = 12kg + 2i.
__global__ void pack_weights(const float* __restrict__ W_hh)
{
    int e = blockIdx.x * blockDim.x + threadIdx.x;
    if (e >= 432) return;
    int b = e & 7, ji = e >> 3;
    int j = ji / 6, i = ji % 6;
    int q = b >> 1, kg = b & 1;
    int gate = j / 3, p = j % 3;
    int r0 = gate * 24 + 6 * q + 2 * p;
    int u0 = 12 * kg + 2 * i;
    g_wq[2 * e]     = pack2(W_hh[r0 * HID + u0],     W_hh[(r0 + 1) * HID + u0]);
    g_wq[2 * e + 1] = pack2(W_hh[r0 * HID + u0 + 1], W_hh[(r0 + 1) * HID + u0 + 1]);
}

__global__ void __launch_bounds__(TPB, 7)
trendgru_kernel(const float* __restrict__ x,
                const float* __restrict__ W_ih,
                const float* __restrict__ b_ih,
                const float* __restrict__ b_hh,
                const float* __restrict__ fc_w,
                const float* __restrict__ fc_b,
                float* __restrict__ out,
                int B, int T)
{
    __shared__ __align__(16) ulonglong2 cRZ[4][6];  // (W_ih pair, b_ih+b_hh pair)
    __shared__ __align__(16) ulonglong2 cN[4][3];   // (W_ih pair, b_ih pair)
    __shared__ u64 cNH[4][3];                       // b_hh n pairs

    const int tid = threadIdx.x;
    if (tid < 24) {
        int qq = tid / 6, j6 = tid % 6;
        int gate = j6 / 3, p = j6 % 3;
        int r0 = gate * 24 + 6 * qq + 2 * p;
        cRZ[qq][j6].x = pack2(W_ih[r0], W_ih[r0 + 1]);
        cRZ[qq][j6].y = pack2(b_ih[r0] + b_hh[r0], b_ih[r0 + 1] + b_hh[r0 + 1]);
    }
    if (tid < 12) {
        int qq = tid / 3, p = tid % 3;
        int r0 = 48 + 6 * qq + 2 * p;
        cN[qq][p].x = pack2(W_ih[r0], W_ih[r0 + 1]);
        cN[qq][p].y = pack2(b_ih[r0], b_ih[r0 + 1]);
        cNH[qq][p]  = pack2(b_hh[r0], b_hh[r0 + 1]);
    }
    __syncthreads();

    // lane layout: cohort = lane>>3 (4 seqs each), q = lane&3 (gate quarter),
    // half = (lane>>2)&1 (k-half). kgroup this thread multiplies: (q>>1)^half.
    const int lane   = tid & 31;
    const int cohort = lane >> 3;
    const int q      = lane & 3;
    const int half   = (lane >> 2) & 1;
    const int kg     = (q >> 1) ^ half;
    const ulonglong2* wg =
        reinterpret_cast<const ulonglong2*>(g_wq) + (q * 2 + kg);  // + 8*(j*6+i)

    const int gcoh  = (blockIdx.x * TPB + tid) >> 3;
    const int sbase = gcoh * 4;
    const float* xr0 = x + (size_t)(sbase + 2 * half) * T;
    const float* xr1 = xr0 + T;

    u64 hown[2][3];     // own h pairs (units 6q..6q+5) for slots 0,1
    #pragma unroll
    for (int mo = 0; mo < 2; mo++)
        #pragma unroll
        for (int p = 0; p < 3; p++) hown[mo][p] = 0ULL;

    for (int t = 0; t < T; t++) {
        const float xa = __ldg(xr0 + t);
        const float xb = __ldg(xr1 + t);
        u64 x2[2];
        x2[0] = pack2(xa, xa);
        x2[1] = pack2(xb, xb);

        u64 acc[4][9];

        // ---- matvec partials over this thread's 12 k-units, all 4 seq slots
        #pragma unroll
        for (int i = 0; i < 6; i++) {
            const int p = i % 3;
            const int srcq = 2 * kg + ((i >= 3) ? 1 : 0);
            u64 e0[4], e1[4];
            #pragma unroll
            for (int m = 0; m < 4; m++) {
                const int mo = m & 1;
                const int hs = half ^ (m >> 1);
                const int src = 8 * cohort + srcq + 4 * hs;
                const u64 hv = __shfl_sync(0xFFFFFFFFu, hown[mo][p], src);
                float h0, h1; unpack2(hv, h0, h1);
                e0[m] = pack2(h0, h0);
                e1[m] = pack2(h1, h1);
            }
            #pragma unroll
            for (int j = 0; j < 9; j++) {
                const ulonglong2 w = __ldg(wg + 8 * (j * 6 + i));
                #pragma unroll
                for (int m = 0; m < 4; m++) {
                    if (i == 0)
                        acc[m][j] = ffma2(w.y, e1[m], fmul2(w.x, e0[m]));
                    else
                        acc[m][j] = ffma2(w.x, e0[m], ffma2(w.y, e1[m], acc[m][j]));
                }
            }
        }

        // ---- reduce k-halves: my slots 0,1 <- + partner's slots 2,3
        #pragma unroll
        for (int j = 0; j < 9; j++)
            #pragma unroll
            for (int mo = 0; mo < 2; mo++)
                acc[mo][j] = fadd2(acc[mo][j],
                                   __shfl_xor_sync(0xFFFFFFFFu, acc[2 + mo][j], 4));

        // ---- gates + h update for slots 0,1 (own units), direct-rcp sigmoids
        #pragma unroll
        for (int mo = 0; mo < 2; mo++) {
            #pragma unroll
            for (int p = 0; p < 3; p++) {
                const ulonglong2 wr = cRZ[q][p];
                const u64 rpre = fadd2(acc[mo][p],     ffma2(wr.x, x2[mo], wr.y));
                const ulonglong2 wz = cRZ[q][3 + p];
                const u64 zpre = fadd2(acc[mo][3 + p], ffma2(wz.x, x2[mo], wz.y));
                const u64 hn   = fadd2(acc[mo][6 + p], cNH[q][p]);
                const ulonglong2 wn = cN[q][p];
                const u64 xn   = ffma2(wn.x, x2[mo], wn.y);

                float a0, a1, c0, c1;
                unpack2(rpre, a0, a1);
                unpack2(zpre, c0, c1);
                const float r0 = rcpa(1.0f + ex2a(a0 * -1.442695041f));
                const float r1 = rcpa(1.0f + ex2a(a1 * -1.442695041f));
                const float z0 = rcpa(1.0f + ex2a(c0 * -1.442695041f));
                const float z1 = rcpa(1.0f + ex2a(c1 * -1.442695041f));

                float hn0, hn1, xn0, xn1;
                unpack2(hn, hn0, hn1);
                unpack2(xn, xn0, xn1);
                const float an0 = fmaf(r0, hn0, xn0);
                const float an1 = fmaf(r1, hn1, xn1);
                const float n0 = fmaf(2.0f, rcpa(1.0f + ex2a(an0 * -2.885390082f)), -1.0f);
                const float n1 = fmaf(2.0f, rcpa(1.0f + ex2a(an1 * -2.885390082f)), -1.0f);

                float ho0, ho1; unpack2(hown[mo][p], ho0, ho1);
                hown[mo][p] = pack2(fmaf(z0, ho0 - n0, n0),
                                    fmaf(z1, ho1 - n1, n1));
            }
        }
    }

    // ---- final fc: partials over own 6 units for slots 0,1; reduce over q lanes
    float p00 = 0.f, p01 = 0.f, p10 = 0.f, p11 = 0.f;   // [slot][out]
    #pragma unroll
    for (int p = 0; p < 3; p++) {
        const int k = 6 * q + 2 * p;
        const float w00 = __ldg(fc_w + k),      w01 = __ldg(fc_w + k + 1);
        const float w10 = __ldg(fc_w + 24 + k), w11 = __ldg(fc_w + 24 + k + 1);
        float e0, e1;
        unpack2(hown[0][p], e0, e1);
        p00 += w00 * e0 + w01 * e1;
        p01 += w10 * e0 + w11 * e1;
        unpack2(hown[1][p], e0, e1);
        p10 += w00 * e0 + w01 * e1;
        p11 += w10 * e0 + w11 * e1;
    }
    #pragma unroll
    for (int off = 1; off < 4; off <<= 1) {   // xor 1,2: stays within same half
        p00 += __shfl_xor_sync(0xFFFFFFFFu, p00, off);
        p01 += __shfl_xor_sync(0xFFFFFFFFu, p01, off);
        p10 += __shfl_xor_sync(0xFFFFFFFFu, p10, off);
        p11 += __shfl_xor_sync(0xFFFFFFFFu, p11, off);
    }
    if (q == 0) {
        const float fb0 = __ldg(fc_b + 0), fb1 = __ldg(fc_b + 1);
        const int sA = sbase + 2 * half;
        out[2 * sA + 0] = p00 + fb0;
        out[2 * sA + 1] = p01 + fb1;
        out[2 * sA + 2] = p10 + fb0;
        out[2 * sA + 3] = p11 + fb1;
    }
}

extern "C" void kernel_launch(void* const* d_in, const int* in_sizes, int n_in,
                              void* d_out, int out_size)
{
    const float* x    = (const float*)d_in[0];
    const float* W_ih = (const float*)d_in[1];
    const float* b_ih = (const float*)d_in[2];
    const float* W_hh = (const float*)d_in[3];
    const float* b_hh = (const float*)d_in[4];
    const float* fc_w = (const float*)d_in[5];
    const float* fc_b = (const float*)d_in[6];
    float* out = (float*)d_out;

    const int B = out_size / 2;
    const int T = in_sizes[0] / B;

    pack_weights<<<2, 256>>>(W_hh);

    const int threads_total = (B / 4) * 8;    // 8 threads/seq, 4 seqs per cohort
    const int grid = threads_total / TPB;
    trendgru_kernel<<<grid, TPB>>>(x, W_ih, b_ih, b_hh, fc_w, fc_b, out, B, T);
}

// round 9
// speedup vs baseline: 1.0458x; 1.0458x over previous
#include <cuda_runtime.h>

#define HID 24
#define TPB 128

typedef unsigned long long u64;

__device__ __forceinline__ u64 pack2(float x, float y) {
    u64 r; asm("mov.b64 %0, {%1, %2};" : "=l"(r) : "f"(x), "f"(y)); return r;
}
__device__ __forceinline__ void unpack2(u64 v, float &x, float &y) {
    asm("mov.b64 {%0, %1}, %2;" : "=f"(x), "=f"(y) : "l"(v));
}
__device__ __forceinline__ u64 ffma2(u64 a, u64 b, u64 c) {
    u64 d; asm("fma.rn.f32x2 %0, %1, %2, %3;" : "=l"(d) : "l"(a), "l"(b), "l"(c)); return d;
}
__device__ __forceinline__ u64 fadd2(u64 a, u64 b) {
    u64 d; asm("add.rn.f32x2 %0, %1, %2;" : "=l"(d) : "l"(a), "l"(b)); return d;
}
__device__ __forceinline__ float ex2a(float x) {
    float r; asm("ex2.approx.f32 %0, %1;" : "=f"(r) : "f"(x)); return r;
}
__device__ __forceinline__ float rcpa(float x) {
    float r; asm("rcp.approx.f32 %0, %1;" : "=f"(r) : "f"(x)); return r;
}
__device__ __forceinline__ float sig_f(float v) {
    return rcpa(1.0f + ex2a(v * -1.442695041f));
}
__device__ __forceinline__ float tanh_f(float v) {
    return fmaf(2.0f, rcpa(1.0f + ex2a(v * -2.885390082f)), -1.0f);
}

// CTA: 4 warps = 4 gate-quarters; warp q owns gate rows {r,z,n}x[6q,6q+6) and
// hidden units 6q..6q+5. Lane m carries seqs (cta*64 + 2m, +1).
// All weight LDS are WARP-UNIFORM (1 distinct address -> ~1.8 cyc each).
__global__ void __launch_bounds__(TPB, 4)
trendgru_kernel(const float* __restrict__ x,
                const float* __restrict__ W_ih,
                const float* __restrict__ b_ih,
                const float* __restrict__ W_hh,
                const float* __restrict__ b_hh,
                const float* __restrict__ fc_w,
                const float* __restrict__ fc_b,
                float* __restrict__ out,
                int B, int T)
{
    // sW u64 index e = (((qq*6+c)*9+j)*2+u)*2+half
    // value = pack2(W_hh[r0][k], W_hh[r0+1][k]), r0 = (j/3)*24 + 6qq + 2(j%3),
    // k = 4c + 2u + half.  One qq block = 216 u64 = 108 ulonglong2.
    __shared__ __align__(16) u64 sW[864];                // 6912 B
    __shared__ __align__(16) ulonglong2 sRZ[4][6];       // (W_ih pair, b_ih+b_hh pair)
    __shared__ __align__(16) ulonglong2 sN[4][3];        // (W_ih_n pair, b_ih_n pair)
    __shared__ u64 sNH[4][3];                            // b_hh n pairs
    __shared__ __align__(16) ulonglong2 hbw[3][12][32];  // h ring: [buf][pair][lane]{A,B}
    __shared__ float fcs[4][32][2][2];                   // fc partials [q][m][s][o]

    const int tid = threadIdx.x;
    const int q   = tid >> 5;
    const int m   = tid & 31;

    for (int e = tid; e < 864; e += TPB) {
        int half = e & 1, v = e >> 1;
        int u = v & 1, v2 = v >> 1;
        int j = v2 % 9, v3 = v2 / 9;
        int c = v3 % 6, qq = v3 / 6;
        int gate = j / 3, p = j % 3;
        int r0 = gate * 24 + 6 * qq + 2 * p;
        int k  = 4 * c + 2 * u + half;
        sW[e] = pack2(W_hh[r0 * HID + k], W_hh[(r0 + 1) * HID + k]);
    }
    if (tid < 24) {
        int qq = tid / 6, j6 = tid % 6;
        int gate = j6 / 3, p = j6 % 3;
        int r0 = gate * 24 + 6 * qq + 2 * p;
        sRZ[qq][j6].x = pack2(W_ih[r0], W_ih[r0 + 1]);
        sRZ[qq][j6].y = pack2(b_ih[r0] + b_hh[r0], b_ih[r0 + 1] + b_hh[r0 + 1]);
    }
    if (tid < 12) {
        int qq = tid / 3, p = tid % 3;
        int r0 = 48 + 6 * qq + 2 * p;
        sN[qq][p].x = pack2(W_ih[r0], W_ih[r0 + 1]);
        sN[qq][p].y = pack2(b_ih[r0], b_ih[r0 + 1]);
        sNH[qq][p]  = pack2(b_hh[r0], b_hh[r0 + 1]);
    }
    // zero h ring buffer 0 (t=0 reads it)
    for (int i = tid; i < 12 * 32; i += TPB)
        hbw[0][i >> 5][i & 31] = make_ulonglong2(0ULL, 0ULL);
    __syncthreads();

    // each quarter block = 108 ulonglong2 (FIX: was q*54)
    const ulonglong2* wq = reinterpret_cast<const ulonglong2*>(sW) + q * 108;

    const int sA = blockIdx.x * 64 + 2 * m;
    const float* xrA = x + (size_t)sA * T;
    const float* xrB = xrA + T;

    const u64 SGN2 = 0x8000000080000000ULL;

    float xA = __ldg(xrA);
    float xB = __ldg(xrB);
    int rb = 0, wb = 1;

    for (int t = 0; t < T; t++) {
        const int tn = (t + 1 < T) ? (t + 1) : t;
        const float xAn = __ldg(xrA + tn);
        const float xBn = __ldg(xrB + tn);

        const u64 x2A = pack2(xA, xA);
        const u64 x2B = pack2(xB, xB);

        u64 acc[2][9], xn[2][3];
        #pragma unroll
        for (int j6 = 0; j6 < 6; j6++) {
            const ulonglong2 w = sRZ[q][j6];
            acc[0][j6] = ffma2(w.x, x2A, w.y);
            acc[1][j6] = ffma2(w.x, x2B, w.y);
        }
        #pragma unroll
        for (int p = 0; p < 3; p++) {
            const ulonglong2 wn = sN[q][p];
            xn[0][p] = ffma2(wn.x, x2A, wn.y);
            xn[1][p] = ffma2(wn.x, x2B, wn.y);
            const u64 bv = sNH[q][p];
            acc[0][6 + p] = bv;
            acc[1][6 + p] = bv;
        }

        // matvec: 6 k-chunks of 4 scalars; weight loads warp-uniform
        #pragma unroll
        for (int c = 0; c < 6; c++) {
            const ulonglong2 ha = hbw[rb][2 * c][m];      // pair 2c  {A,B}
            const ulonglong2 hb = hbw[rb][2 * c + 1][m];  // pair 2c+1{A,B}
            float A0, A1, A2, A3, B0, B1, B2, B3;
            unpack2(ha.x, A0, A1); unpack2(hb.x, A2, A3);
            unpack2(ha.y, B0, B1); unpack2(hb.y, B2, B3);
            const u64 eA0 = pack2(A0, A0), eA1 = pack2(A1, A1);
            const u64 eA2 = pack2(A2, A2), eA3 = pack2(A3, A3);
            const u64 eB0 = pack2(B0, B0), eB1 = pack2(B1, B1);
            const u64 eB2 = pack2(B2, B2), eB3 = pack2(B3, B3);
            #pragma unroll
            for (int j = 0; j < 9; j++) {
                const ulonglong2 w0 = wq[(c * 9 + j) * 2];      // k = 4c, 4c+1
                const ulonglong2 w1 = wq[(c * 9 + j) * 2 + 1];  // k = 4c+2, 4c+3
                acc[0][j] = ffma2(w0.x, eA0, acc[0][j]);
                acc[0][j] = ffma2(w0.y, eA1, acc[0][j]);
                acc[0][j] = ffma2(w1.x, eA2, acc[0][j]);
                acc[0][j] = ffma2(w1.y, eA3, acc[0][j]);
                acc[1][j] = ffma2(w0.x, eB0, acc[1][j]);
                acc[1][j] = ffma2(w0.y, eB1, acc[1][j]);
                acc[1][j] = ffma2(w1.x, eB2, acc[1][j]);
                acc[1][j] = ffma2(w1.y, eB3, acc[1][j]);
            }
        }

        // gates + h update for own 3 pairs, both seqs
        #pragma unroll
        for (int p = 0; p < 3; p++) {
            const ulonglong2 hold = hbw[rb][3 * q + p][m];
            u64 hnew[2];
            #pragma unroll
            for (int s = 0; s < 2; s++) {
                float a0, a1, c0, c1;
                unpack2(acc[s][p], a0, a1);
                unpack2(acc[s][3 + p], c0, c1);
                const u64 r2 = pack2(sig_f(a0), sig_f(a1));
                const u64 z2 = pack2(sig_f(c0), sig_f(c1));
                const u64 npre = ffma2(r2, acc[s][6 + p], xn[s][p]);
                float n0, n1; unpack2(npre, n0, n1);
                const u64 n2 = pack2(tanh_f(n0), tanh_f(n1));
                const u64 hp = (s == 0) ? hold.x : hold.y;
                hnew[s] = ffma2(z2, fadd2(hp, n2 ^ SGN2), n2);
            }
            hbw[wb][3 * q + p][m] = make_ulonglong2(hnew[0], hnew[1]);
        }

        __syncthreads();
        xA = xAn;
        xB = xBn;
        rb = wb;
        wb = (wb == 2) ? 0 : (wb + 1);
    }

    // final fc: partials over own 6 units, combine across warps via SMEM
    float p0A = 0.f, p1A = 0.f, p0B = 0.f, p1B = 0.f;
    #pragma unroll
    for (int p = 0; p < 3; p++) {
        const int k = 6 * q + 2 * p;
        const float w00 = __ldg(fc_w + k),      w01 = __ldg(fc_w + k + 1);
        const float w10 = __ldg(fc_w + 24 + k), w11 = __ldg(fc_w + 24 + k + 1);
        const ulonglong2 hold = hbw[rb][3 * q + p][m];
        float e0, e1;
        unpack2(hold.x, e0, e1);
        p0A += w00 * e0 + w01 * e1;
        p1A += w10 * e0 + w11 * e1;
        unpack2(hold.y, e0, e1);
        p0B += w00 * e0 + w01 * e1;
        p1B += w10 * e0 + w11 * e1;
    }
    fcs[q][m][0][0] = p0A;
    fcs[q][m][0][1] = p1A;
    fcs[q][m][1][0] = p0B;
    fcs[q][m][1][1] = p1B;
    __syncthreads();

    if (q == 0) {
        const float fb0 = __ldg(fc_b + 0), fb1 = __ldg(fc_b + 1);
        float o0A = fb0, o1A = fb1, o0B = fb0, o1B = fb1;
        #pragma unroll
        for (int qq = 0; qq < 4; qq++) {
            o0A += fcs[qq][m][0][0];
            o1A += fcs[qq][m][0][1];
            o0B += fcs[qq][m][1][0];
            o1B += fcs[qq][m][1][1];
        }
        out[2 * sA + 0] = o0A;
        out[2 * sA + 1] = o1A;
        out[2 * sA + 2] = o0B;
        out[2 * sA + 3] = o1B;
    }
}

extern "C" void kernel_launch(void* const* d_in, const int* in_sizes, int n_in,
                              void* d_out, int out_size)
{
    const float* x    = (const float*)d_in[0];
    const float* W_ih = (const float*)d_in[1];
    const float* b_ih = (const float*)d_in[2];
    const float* W_hh = (const float*)d_in[3];
    const float* b_hh = (const float*)d_in[4];
    const float* fc_w = (const float*)d_in[5];
    const float* fc_b = (const float*)d_in[6];
    float* out = (float*)d_out;

    const int B = out_size / 2;
    const int T = in_sizes[0] / B;

    const int grid = B / 64;   // 64 seqs per CTA
    trendgru_kernel<<<grid, TPB>>>(x, W_ih, b_ih, W_hh, b_hh, fc_w, fc_b, out, B, T);
}